// round 2
// baseline (speedup 1.0000x reference)
#include <cuda_runtime.h>
#include <cuda_bf16.h>
#include <cstdint>

#define E_   8
#define CAP_ 2048
#define D_   1024
#define H_   4096

// ---------------- scratch (device globals; no runtime allocation) ----------------
__device__ __nv_bfloat16 g_X2 [(size_t)E_ * CAP_ * (2 * D_)];   // [E*2048][2048]  hi|lo
__device__ __nv_bfloat16 g_W1s[(size_t)E_ * H_   * (2 * D_)];   // [E*4096][2048]  hi|lo
__device__ __nv_bfloat16 g_W2T[(size_t)E_ * D_   * (2 * H_)];   // [E*1024][8192]  hi|lo (W2^T)
__device__ __nv_bfloat16 g_Y2 [(size_t)E_ * CAP_ * (2 * H_)];   // [E*2048][8192]  hi|lo

// ---------------- PTX helpers (portable: sm_80+ features only) ----------------
__device__ __forceinline__ uint32_t smem_u32(const void* p) {
    uint32_t a;
    asm("{ .reg .u64 t; cvta.to.shared.u64 t, %1; cvt.u32.u64 %0, t; }" : "=r"(a) : "l"(p));
    return a;
}
__device__ __forceinline__ void cpa16(uint32_t s, const void* g) {
    asm volatile("cp.async.cg.shared.global [%0], [%1], 16;" :: "r"(s), "l"(g) : "memory");
}
__device__ __forceinline__ void ldsm4(uint32_t r[4], uint32_t addr) {
    asm volatile("ldmatrix.sync.aligned.m8n8.x4.shared.b16 {%0,%1,%2,%3}, [%4];"
                 : "=r"(r[0]), "=r"(r[1]), "=r"(r[2]), "=r"(r[3]) : "r"(addr));
}
__device__ __forceinline__ void mma16816(float d[4], const uint32_t a[4],
                                         uint32_t b0, uint32_t b1) {
    asm volatile("mma.sync.aligned.m16n8k16.row.col.f32.bf16.bf16.f32 "
                 "{%0,%1,%2,%3},{%4,%5,%6,%7},{%8,%9},{%0,%1,%2,%3};"
                 : "+f"(d[0]), "+f"(d[1]), "+f"(d[2]), "+f"(d[3])
                 : "r"(a[0]), "r"(a[1]), "r"(a[2]), "r"(a[3]), "r"(b0), "r"(b1));
}
__device__ __forceinline__ uint32_t b2u(__nv_bfloat162 h) {
    return *reinterpret_cast<uint32_t*>(&h);
}

// ---------------- split kernels: fp32 -> bf16 hi|lo (K=1024 rows) ----------------
template<int TGT>
__global__ void split_hilo(const float* __restrict__ src) {
    __nv_bfloat16* dst = (TGT == 0) ? g_X2 : g_W1s;
    size_t t = (size_t)blockIdx.x * 256 + threadIdx.x;   // one float4 per thread
    int row = (int)(t >> 8);
    int kq  = (int)(t & 255);
    float4 v = *((const float4*)src + t);
    __nv_bfloat162 h0 = __floats2bfloat162_rn(v.x, v.y);
    __nv_bfloat162 h1 = __floats2bfloat162_rn(v.z, v.w);
    __nv_bfloat162 l0 = __floats2bfloat162_rn(v.x - __bfloat162float(h0.x),
                                              v.y - __bfloat162float(h0.y));
    __nv_bfloat162 l1 = __floats2bfloat162_rn(v.z - __bfloat162float(h1.x),
                                              v.w - __bfloat162float(h1.y));
    __nv_bfloat16* drow = dst + (size_t)row * 2048;
    *(uint2*)(drow + kq * 4)        = make_uint2(b2u(h0), b2u(h1));
    *(uint2*)(drow + 1024 + kq * 4) = make_uint2(b2u(l0), b2u(l1));
}

// ---------------- W2 transpose + split: [E,H,D] fp32 -> [E,D][2H] bf16 hi|lo ----------------
__global__ void split_w2t(const float* __restrict__ w2) {
    __shared__ float tile[32][33];
    int e  = blockIdx.z;
    int d0 = blockIdx.x * 32;
    int h0 = blockIdx.y * 32;
    int tx = threadIdx.x, ty = threadIdx.y;
#pragma unroll
    for (int r = 0; r < 4; r++) {
        int h = h0 + ty + r * 8;
        tile[ty + r * 8][tx] = w2[((size_t)(e * H_ + h)) * D_ + d0 + tx];
    }
    __syncthreads();
#pragma unroll
    for (int r = 0; r < 4; r++) {
        int d = d0 + ty + r * 8;
        int h = h0 + tx;
        float v = tile[tx][ty + r * 8];
        __nv_bfloat16 hi = __float2bfloat16(v);
        __nv_bfloat16 lo = __float2bfloat16(v - __bfloat162float(hi));
        size_t base = ((size_t)(e * D_ + d)) * (2 * H_);
        g_W2T[base + h]      = hi;
        g_W2T[base + H_ + h] = lo;
    }
}

// ---------------- 3-term bf16 GEMM via mma.sync (sm80-style cp.async pipeline) ----------------
// PHASE 1: g_X2[2048,2K] x g_W1s[4096,2K]^T  -> relu(+b1) -> split -> g_Y2
// PHASE 2: g_Y2[2048,2K'] x g_W2T[1024,2K']^T -> +b2 -> outF (fp32)
#define STAGES 3
#define STB    32768                       // per-stage: A 16KB + B 16KB
#define SMEM_TOT (STAGES * STB)            // 96 KB

template<int PHASE>
__global__ void __launch_bounds__(256, 2) gemm_mma(const float* __restrict__ bias,
                                                   float* __restrict__ outF) {
    constexpr int Ntot = (PHASE == 1) ? H_ : D_;
    constexpr int KSEG = (PHASE == 1) ? D_ : H_;
    constexpr int LDA  = 2 * KSEG;         // row stride of [hi|lo] layout (elements)
    constexpr int CS   = KSEG / 64;        // 64-wide K chunks per segment
    constexpr int NCH  = 3 * CS;           // 3 terms
    constexpr int Mt   = CAP_ / 128;
    constexpr int Nt   = Ntot / 128;

    extern __shared__ char smem[];
    const uint32_t sb = smem_u32(smem);
    const int tid = threadIdx.x, wid = tid >> 5, lane = tid & 31;

    const int idx = blockIdx.x;
    const int mt = idx % Mt;
    const int nt = (idx / Mt) % Nt;
    const int e  = idx / (Mt * Nt);
    const int m0 = mt * 128, n0 = nt * 128;

    const __nv_bfloat16* A = (PHASE == 1) ? g_X2  : g_Y2;
    const __nv_bfloat16* B = (PHASE == 1) ? g_W1s : g_W2T;
    const __nv_bfloat16* Ab = A + (size_t)(e * CAP_ + m0) * LDA;
    const __nv_bfloat16* Bb = B + (size_t)(e * Ntot + n0) * LDA;

    // per-thread gmem->smem coords: 1024 16B-chunks per tile, 4 per thread
    // i = t*256+tid: row = i>>3 (128 rows), c16 = i&7 (8 chunks of 16B per 64-elem row)
    auto issue = [&](int c) {
        const int p = c / CS, r = c - p * CS;
        const int a_k = (p == 1 ? KSEG : 0) + r * 64;  // A segs: hi, lo, hi
        const int b_k = (p == 2 ? KSEG : 0) + r * 64;  // B segs: hi, hi, lo
        const int st = c % STAGES;
        const uint32_t sA = sb + st * STB, sB = sA + 16384;
#pragma unroll
        for (int t = 0; t < 4; t++) {
            int i = t * 256 + tid, row = i >> 3, c16 = i & 7;
            cpa16(sA + row * 128 + ((c16 ^ (row & 7)) << 4),
                  Ab + (size_t)row * LDA + a_k + c16 * 8);
        }
#pragma unroll
        for (int t = 0; t < 4; t++) {
            int i = t * 256 + tid, row = i >> 3, c16 = i & 7;
            cpa16(sB + row * 128 + ((c16 ^ (row & 7)) << 4),
                  Bb + (size_t)row * LDA + b_k + c16 * 8);
        }
        asm volatile("cp.async.commit_group;" ::: "memory");
    };

    // warp tile: 32 (M) x 64 (N); warp grid 4x2
    const int m_off = (wid >> 1) * 32;
    const int n_off = (wid & 1) * 64;
    float acc[2][8][4] = {};

    issue(0);
    issue(1);
    asm volatile("cp.async.wait_group 1;" ::: "memory");
    __syncthreads();

    for (int c = 0; c < NCH; ++c) {
        const int st = c % STAGES;
        const uint32_t sA = sb + st * STB, sB = sA + 16384;
#pragma unroll
        for (int kk = 0; kk < 4; ++kk) {               // 4 x k16 per 64-chunk
            uint32_t aF[2][4];
#pragma unroll
            for (int i = 0; i < 2; ++i) {
                int row = m_off + 16 * i + (lane & 15);
                int ch  = kk * 2 + (lane >> 4);
                ldsm4(aF[i], sA + row * 128 + ((ch ^ (row & 7)) << 4));
            }
            uint32_t bF[4][4];
#pragma unroll
            for (int j4 = 0; j4 < 4; ++j4) {
                int row = n_off + 16 * j4 + ((lane >> 4) << 3) + (lane & 7);
                int ch  = kk * 2 + ((lane >> 3) & 1);
                ldsm4(bF[j4], sB + row * 128 + ((ch ^ (row & 7)) << 4));
            }
#pragma unroll
            for (int i = 0; i < 2; ++i)
#pragma unroll
                for (int j = 0; j < 8; ++j)
                    mma16816(acc[i][j], aF[i], bF[j >> 1][(j & 1) * 2], bF[j >> 1][(j & 1) * 2 + 1]);
        }
        if (c + 2 < NCH) issue(c + 2);
        else asm volatile("cp.async.commit_group;" ::: "memory");
        asm volatile("cp.async.wait_group 1;" ::: "memory");
        __syncthreads();
    }

    // ---- epilogue ----
    const int r_lane = lane >> 2;
    const int c_lane = (lane & 3) * 2;
    const float* brow = bias + (size_t)e * Ntot;
#pragma unroll
    for (int i = 0; i < 2; ++i) {
#pragma unroll
        for (int half = 0; half < 2; ++half) {
            const int m = m0 + m_off + 16 * i + r_lane + half * 8;
            if (PHASE == 1) {
                __nv_bfloat16* yrow = g_Y2 + (size_t)(e * CAP_ + m) * (2 * H_);
#pragma unroll
                for (int j = 0; j < 8; ++j) {
                    const int col = n0 + n_off + 8 * j + c_lane;
                    float v0 = acc[i][j][half * 2 + 0] + brow[col];
                    float v1 = acc[i][j][half * 2 + 1] + brow[col + 1];
                    v0 = fmaxf(v0, 0.f);
                    v1 = fmaxf(v1, 0.f);
                    __nv_bfloat162 h2 = __floats2bfloat162_rn(v0, v1);
                    __nv_bfloat162 l2 = __floats2bfloat162_rn(v0 - __bfloat162float(h2.x),
                                                              v1 - __bfloat162float(h2.y));
                    *(uint32_t*)(yrow + col)      = b2u(h2);
                    *(uint32_t*)(yrow + H_ + col) = b2u(l2);
                }
            } else {
                float* orow = outF + (size_t)(e * CAP_ + m) * D_;
#pragma unroll
                for (int j = 0; j < 8; ++j) {
                    const int col = n0 + n_off + 8 * j + c_lane;
                    float2 f;
                    f.x = acc[i][j][half * 2 + 0] + brow[col];
                    f.y = acc[i][j][half * 2 + 1] + brow[col + 1];
                    *(float2*)(orow + col) = f;
                }
            }
        }
    }
}

// ---------------- launch ----------------
extern "C" void kernel_launch(void* const* d_in, const int* in_sizes, int n_in,
                              void* d_out, int out_size) {
    const float* x  = (const float*)d_in[0];   // [E, CAP, D]
    const float* w1 = (const float*)d_in[1];   // [E, H, D]
    const float* b1 = (const float*)d_in[2];   // [E, H]
    const float* w2 = (const float*)d_in[3];   // [E, H, D]
    const float* b2 = (const float*)d_in[4];   // [E, D]
    float* out = (float*)d_out;                // [E, CAP, D]

    cudaFuncSetAttribute(gemm_mma<1>, cudaFuncAttributeMaxDynamicSharedMemorySize, SMEM_TOT);
    cudaFuncSetAttribute(gemm_mma<2>, cudaFuncAttributeMaxDynamicSharedMemorySize, SMEM_TOT);

    // 1) precision splits
    split_hilo<0><<<E_ * CAP_, 256>>>(x);                         // X  -> g_X2
    split_hilo<1><<<E_ * H_,   256>>>(w1);                        // W1 -> g_W1s
    split_w2t<<<dim3(D_ / 32, H_ / 32, E_), dim3(32, 8)>>>(w2);   // W2 -> g_W2T

    // 2) GEMM1: relu(X W1^T + b1) -> g_Y2 (bf16 hi|lo)
    gemm_mma<1><<<E_ * (CAP_ / 128) * (H_ / 128), 256, SMEM_TOT>>>(b1, nullptr);

    // 3) GEMM2: Y W2 + b2 -> out (fp32)
    gemm_mma<2><<<E_ * (CAP_ / 128) * (D_ / 128), 256, SMEM_TOT>>>(b2, out);
}

// round 3
// speedup vs baseline: 1.4822x; 1.4822x over previous
#include <cuda_runtime.h>
#include <cuda_fp16.h>
#include <cstdint>

#define E_   8
#define CAP_ 2048
#define D_   1024
#define H_   4096

// ---------------- scratch (device globals; no runtime allocation) ----------------
__device__ __half g_Xh [(size_t)E_ * CAP_ * D_];        // [E*2048][1024]  plain fp16
__device__ __half g_W1s[(size_t)E_ * H_   * (2 * D_)];  // [E*4096][2048]  hi|lo
__device__ __half g_W2T[(size_t)E_ * D_   * (2 * H_)];  // [E*1024][8192]  hi|lo (W2^T)
__device__ __half g_Y  [(size_t)E_ * CAP_ * H_];        // [E*2048][4096]  plain fp16

// ---------------- PTX helpers (portable: sm_80+ features only) ----------------
__device__ __forceinline__ uint32_t smem_u32(const void* p) {
    uint32_t a;
    asm("{ .reg .u64 t; cvta.to.shared.u64 t, %1; cvt.u32.u64 %0, t; }" : "=r"(a) : "l"(p));
    return a;
}
__device__ __forceinline__ void cpa16(uint32_t s, const void* g) {
    asm volatile("cp.async.cg.shared.global [%0], [%1], 16;" :: "r"(s), "l"(g) : "memory");
}
__device__ __forceinline__ void ldsm4(uint32_t r[4], uint32_t addr) {
    asm volatile("ldmatrix.sync.aligned.m8n8.x4.shared.b16 {%0,%1,%2,%3}, [%4];"
                 : "=r"(r[0]), "=r"(r[1]), "=r"(r[2]), "=r"(r[3]) : "r"(addr));
}
__device__ __forceinline__ void mma16816(float d[4], const uint32_t a[4],
                                         uint32_t b0, uint32_t b1) {
    asm volatile("mma.sync.aligned.m16n8k16.row.col.f32.f16.f16.f32 "
                 "{%0,%1,%2,%3},{%4,%5,%6,%7},{%8,%9},{%0,%1,%2,%3};"
                 : "+f"(d[0]), "+f"(d[1]), "+f"(d[2]), "+f"(d[3])
                 : "r"(a[0]), "r"(a[1]), "r"(a[2]), "r"(a[3]), "r"(b0), "r"(b1));
}
__device__ __forceinline__ uint32_t h2u(__half2 h) {
    return *reinterpret_cast<uint32_t*>(&h);
}

// ---------------- X convert: fp32 -> plain fp16 ----------------
__global__ void conv_x(const float* __restrict__ src) {
    size_t t = (size_t)blockIdx.x * 256 + threadIdx.x;   // one float4 per thread
    float4 v = *((const float4*)src + t);
    __half2 h0 = __floats2half2_rn(v.x, v.y);
    __half2 h1 = __floats2half2_rn(v.z, v.w);
    *(uint2*)(g_Xh + t * 4) = make_uint2(h2u(h0), h2u(h1));
}

// ---------------- W1 split: fp32 -> fp16 hi|lo (rows of 1024) ----------------
__global__ void split_w1(const float* __restrict__ src) {
    size_t t = (size_t)blockIdx.x * 256 + threadIdx.x;   // one float4 per thread
    int row = (int)(t >> 8);
    int kq  = (int)(t & 255);
    float4 v = *((const float4*)src + t);
    __half2 h0 = __floats2half2_rn(v.x, v.y);
    __half2 h1 = __floats2half2_rn(v.z, v.w);
    __half2 l0 = __floats2half2_rn(v.x - __half2float(__low2half(h0)),
                                   v.y - __half2float(__high2half(h0)));
    __half2 l1 = __floats2half2_rn(v.z - __half2float(__low2half(h1)),
                                   v.w - __half2float(__high2half(h1)));
    __half* drow = g_W1s + (size_t)row * 2048;
    *(uint2*)(drow + kq * 4)        = make_uint2(h2u(h0), h2u(h1));
    *(uint2*)(drow + 1024 + kq * 4) = make_uint2(h2u(l0), h2u(l1));
}

// ---------------- W2 transpose + split: [E,H,D] fp32 -> [E,D][2H] fp16 hi|lo ----------------
__global__ void split_w2t(const float* __restrict__ w2) {
    __shared__ float tile[32][33];
    int e  = blockIdx.z;
    int d0 = blockIdx.x * 32;
    int h0 = blockIdx.y * 32;
    int tx = threadIdx.x, ty = threadIdx.y;
#pragma unroll
    for (int r = 0; r < 4; r++) {
        int h = h0 + ty + r * 8;
        tile[ty + r * 8][tx] = w2[((size_t)(e * H_ + h)) * D_ + d0 + tx];
    }
    __syncthreads();
#pragma unroll
    for (int r = 0; r < 4; r++) {
        int d = d0 + ty + r * 8;
        int h = h0 + tx;
        float v = tile[tx][ty + r * 8];
        __half hi = __float2half_rn(v);
        __half lo = __float2half_rn(v - __half2float(hi));
        size_t base = ((size_t)(e * D_ + d)) * (2 * H_);
        g_W2T[base + h]      = hi;
        g_W2T[base + H_ + h] = lo;
    }
}

// ---------------- 2-term fp16 GEMM via mma.sync (cp.async pipeline) ----------------
// PHASE 1: g_Xh[2048,K] x g_W1s[4096,2K]^T  -> relu(+b1) -> g_Y (plain fp16)
// PHASE 2: g_Y[2048,K'] x g_W2T[1024,2K']^T -> +b2 -> outF (fp32)
#define STAGES 3
#define STB    32768                       // per-stage: A 16KB + B 16KB
#define SMEM_TOT (STAGES * STB)            // 96 KB

template<int PHASE>
__global__ void __launch_bounds__(256, 2) gemm_mma(const float* __restrict__ bias,
                                                   float* __restrict__ outF) {
    constexpr int Ntot = (PHASE == 1) ? H_ : D_;
    constexpr int KSEG = (PHASE == 1) ? D_ : H_;
    constexpr int LDB  = 2 * KSEG;         // B row stride (hi|lo layout)
    constexpr int CS   = KSEG / 64;        // 64-wide K chunks per segment
    constexpr int NCH  = 2 * CS;           // 2 terms: (A,Bh), (A,Bl)
    constexpr int Mt   = CAP_ / 128;
    constexpr int Nt   = Ntot / 128;

    extern __shared__ char smem[];
    const uint32_t sb = smem_u32(smem);
    const int tid = threadIdx.x, wid = tid >> 5, lane = tid & 31;

    const int idx = blockIdx.x;
    const int mt = idx % Mt;
    const int nt = (idx / Mt) % Nt;
    const int e  = idx / (Mt * Nt);
    const int m0 = mt * 128, n0 = nt * 128;

    const __half* A = (PHASE == 1) ? g_Xh  : g_Y;
    const __half* B = (PHASE == 1) ? g_W1s : g_W2T;
    const __half* Ab = A + (size_t)(e * CAP_ + m0) * KSEG;
    const __half* Bb = B + (size_t)(e * Ntot + n0) * LDB;

    auto issue = [&](int c) {
        const int p = c / CS, r = c - p * CS;
        const int a_k = r * 64;                        // A: same data both segments
        const int b_k = (p ? KSEG : 0) + r * 64;       // B: hi then lo
        const int st = c % STAGES;
        const uint32_t sA = sb + st * STB, sB = sA + 16384;
#pragma unroll
        for (int t = 0; t < 4; t++) {
            int i = t * 256 + tid, row = i >> 3, c16 = i & 7;
            cpa16(sA + row * 128 + ((c16 ^ (row & 7)) << 4),
                  Ab + (size_t)row * KSEG + a_k + c16 * 8);
        }
#pragma unroll
        for (int t = 0; t < 4; t++) {
            int i = t * 256 + tid, row = i >> 3, c16 = i & 7;
            cpa16(sB + row * 128 + ((c16 ^ (row & 7)) << 4),
                  Bb + (size_t)row * LDB + b_k + c16 * 8);
        }
        asm volatile("cp.async.commit_group;" ::: "memory");
    };

    // warp tile: 32 (M) x 64 (N); warp grid 4x2
    const int m_off = (wid >> 1) * 32;
    const int n_off = (wid & 1) * 64;
    float acc[2][8][4] = {};

    issue(0);
    issue(1);
    asm volatile("cp.async.wait_group 1;" ::: "memory");
    __syncthreads();

    for (int c = 0; c < NCH; ++c) {
        const int st = c % STAGES;
        const uint32_t sA = sb + st * STB, sB = sA + 16384;
#pragma unroll
        for (int kk = 0; kk < 4; ++kk) {               // 4 x k16 per 64-chunk
            uint32_t aF[2][4];
#pragma unroll
            for (int i = 0; i < 2; ++i) {
                int row = m_off + 16 * i + (lane & 15);
                int ch  = kk * 2 + (lane >> 4);
                ldsm4(aF[i], sA + row * 128 + ((ch ^ (row & 7)) << 4));
            }
            uint32_t bF[4][4];
#pragma unroll
            for (int j4 = 0; j4 < 4; ++j4) {
                int row = n_off + 16 * j4 + ((lane >> 4) << 3) + (lane & 7);
                int ch  = kk * 2 + ((lane >> 3) & 1);
                ldsm4(bF[j4], sB + row * 128 + ((ch ^ (row & 7)) << 4));
            }
#pragma unroll
            for (int i = 0; i < 2; ++i)
#pragma unroll
                for (int j = 0; j < 8; ++j)
                    mma16816(acc[i][j], aF[i], bF[j >> 1][(j & 1) * 2], bF[j >> 1][(j & 1) * 2 + 1]);
        }
        if (c + 2 < NCH) issue(c + 2);
        else asm volatile("cp.async.commit_group;" ::: "memory");
        asm volatile("cp.async.wait_group 1;" ::: "memory");
        __syncthreads();
    }

    // ---- epilogue ----
    const int r_lane = lane >> 2;
    const int c_lane = (lane & 3) * 2;
    const float* brow = bias + (size_t)e * Ntot;
#pragma unroll
    for (int i = 0; i < 2; ++i) {
#pragma unroll
        for (int half = 0; half < 2; ++half) {
            const int m = m0 + m_off + 16 * i + r_lane + half * 8;
            if (PHASE == 1) {
                __half* yrow = g_Y + (size_t)(e * CAP_ + m) * H_;
#pragma unroll
                for (int j = 0; j < 8; ++j) {
                    const int col = n0 + n_off + 8 * j + c_lane;
                    float v0 = acc[i][j][half * 2 + 0] + brow[col];
                    float v1 = acc[i][j][half * 2 + 1] + brow[col + 1];
                    v0 = fmaxf(v0, 0.f);
                    v1 = fmaxf(v1, 0.f);
                    *(uint32_t*)(yrow + col) = h2u(__floats2half2_rn(v0, v1));
                }
            } else {
                float* orow = outF + (size_t)(e * CAP_ + m) * D_;
#pragma unroll
                for (int j = 0; j < 8; ++j) {
                    const int col = n0 + n_off + 8 * j + c_lane;
                    float2 f;
                    f.x = acc[i][j][half * 2 + 0] + brow[col];
                    f.y = acc[i][j][half * 2 + 1] + brow[col + 1];
                    *(float2*)(orow + col) = f;
                }
            }
        }
    }
}

// ---------------- launch ----------------
extern "C" void kernel_launch(void* const* d_in, const int* in_sizes, int n_in,
                              void* d_out, int out_size) {
    const float* x  = (const float*)d_in[0];   // [E, CAP, D]
    const float* w1 = (const float*)d_in[1];   // [E, H, D]
    const float* b1 = (const float*)d_in[2];   // [E, H]
    const float* w2 = (const float*)d_in[3];   // [E, H, D]
    const float* b2 = (const float*)d_in[4];   // [E, D]
    float* out = (float*)d_out;                // [E, CAP, D]

    cudaFuncSetAttribute(gemm_mma<1>, cudaFuncAttributeMaxDynamicSharedMemorySize, SMEM_TOT);
    cudaFuncSetAttribute(gemm_mma<2>, cudaFuncAttributeMaxDynamicSharedMemorySize, SMEM_TOT);

    // 1) conversions / splits
    conv_x  <<<(E_ * CAP_ * D_ / 4) / 256, 256>>>(x);              // X  -> g_Xh (plain fp16)
    split_w1<<<E_ * H_, 256>>>(w1);                                // W1 -> g_W1s (hi|lo)
    split_w2t<<<dim3(D_ / 32, H_ / 32, E_), dim3(32, 8)>>>(w2);    // W2 -> g_W2T (hi|lo, transposed)

    // 2) GEMM1: relu(X W1^T + b1) -> g_Y (plain fp16)
    gemm_mma<1><<<E_ * (CAP_ / 128) * (H_ / 128), 256, SMEM_TOT>>>(b1, nullptr);

    // 3) GEMM2: Y W2 + b2 -> out (fp32)
    gemm_mma<2><<<E_ * (CAP_ / 128) * (D_ / 128), 256, SMEM_TOT>>>(b2, out);
}

// round 5
// speedup vs baseline: 2.6722x; 1.8028x over previous
#include <cuda_runtime.h>
#include <cuda_fp16.h>
#include <cstdint>

#define E_   8
#define CAP_ 2048
#define D_   1024
#define H_   4096

// ---------------- scratch (device globals; no runtime allocation) ----------------
__device__ __half g_Xh [(size_t)E_ * CAP_ * D_];   // [E*2048][1024]
__device__ __half g_W1h[(size_t)E_ * H_   * D_];   // [E*4096][1024]
__device__ __half g_W2T[(size_t)E_ * D_   * H_];   // [E*1024][4096]  (W2^T)
__device__ __half g_Y  [(size_t)E_ * CAP_ * H_];   // [E*2048][4096]

// ---------------- PTX helpers (portable: sm_80+ features only) ----------------
__device__ __forceinline__ uint32_t smem_u32(const void* p) {
    uint32_t a;
    asm("{ .reg .u64 t; cvta.to.shared.u64 t, %1; cvt.u32.u64 %0, t; }" : "=r"(a) : "l"(p));
    return a;
}
__device__ __forceinline__ void cpa16(uint32_t s, const void* g) {
    asm volatile("cp.async.cg.shared.global [%0], [%1], 16;" :: "r"(s), "l"(g) : "memory");
}
__device__ __forceinline__ void ldsm4(uint32_t r[4], uint32_t addr) {
    asm volatile("ldmatrix.sync.aligned.m8n8.x4.shared.b16 {%0,%1,%2,%3}, [%4];"
                 : "=r"(r[0]), "=r"(r[1]), "=r"(r[2]), "=r"(r[3]) : "r"(addr));
}
__device__ __forceinline__ void mma16816(float d[4], const uint32_t a[4],
                                         uint32_t b0, uint32_t b1) {
    asm volatile("mma.sync.aligned.m16n8k16.row.col.f32.f16.f16.f32 "
                 "{%0,%1,%2,%3},{%4,%5,%6,%7},{%8,%9},{%0,%1,%2,%3};"
                 : "+f"(d[0]), "+f"(d[1]), "+f"(d[2]), "+f"(d[3])
                 : "r"(a[0]), "r"(a[1]), "r"(a[2]), "r"(a[3]), "r"(b0), "r"(b1));
}
__device__ __forceinline__ uint32_t h2u(__half2 h) {
    return *reinterpret_cast<uint32_t*>(&h);
}

// ---------------- convert: fp32 -> fp16 elementwise; dst chosen in DEVICE code ----------------
template<int TGT>   // 0 -> g_Xh, 1 -> g_W1h
__global__ void conv_f16(const float* __restrict__ src) {
    __half* dst = (TGT == 0) ? g_Xh : g_W1h;
    size_t t = (size_t)blockIdx.x * 256 + threadIdx.x;   // one float4 per thread
    float4 v = *((const float4*)src + t);
    __half2 h0 = __floats2half2_rn(v.x, v.y);
    __half2 h1 = __floats2half2_rn(v.z, v.w);
    *(uint2*)(dst + t * 4) = make_uint2(h2u(h0), h2u(h1));
}

// ---------------- W2 transpose + convert: [E,H,D] fp32 -> [E,D][H] fp16 ----------------
__global__ void conv_w2t(const float* __restrict__ w2) {
    __shared__ float tile[32][33];
    int e  = blockIdx.z;
    int d0 = blockIdx.x * 32;
    int h0 = blockIdx.y * 32;
    int tx = threadIdx.x, ty = threadIdx.y;
#pragma unroll
    for (int r = 0; r < 4; r++) {
        int h = h0 + ty + r * 8;
        tile[ty + r * 8][tx] = w2[((size_t)(e * H_ + h)) * D_ + d0 + tx];
    }
    __syncthreads();
#pragma unroll
    for (int r = 0; r < 4; r++) {
        int d = d0 + ty + r * 8;
        int h = h0 + tx;
        g_W2T[((size_t)(e * D_ + d)) * H_ + h] = __float2half_rn(tile[tx][ty + r * 8]);
    }
}

// ---------------- fp16 GEMM via mma.sync (cp.async pipeline) ----------------
// PHASE 1: g_Xh[2048,K] x g_W1h[4096,K]^T -> relu(+b1) -> g_Y (fp16)
// PHASE 2: g_Y[2048,K'] x g_W2T[1024,K']^T -> +b2 -> outF (fp32)
#define STAGES 3
#define STB    32768                       // per-stage: A 16KB + B 16KB
#define SMEM_TOT (STAGES * STB)            // 96 KB

template<int PHASE>
__global__ void __launch_bounds__(256, 2) gemm_mma(const float* __restrict__ bias,
                                                   float* __restrict__ outF) {
    constexpr int Ntot = (PHASE == 1) ? H_ : D_;
    constexpr int KSEG = (PHASE == 1) ? D_ : H_;
    constexpr int NCH  = KSEG / 64;        // 64-wide K chunks
    constexpr int Mt   = CAP_ / 128;
    constexpr int Nt   = Ntot / 128;

    extern __shared__ char smem[];
    const uint32_t sb = smem_u32(smem);
    const int tid = threadIdx.x, wid = tid >> 5, lane = tid & 31;

    const int idx = blockIdx.x;
    const int mt = idx % Mt;
    const int nt = (idx / Mt) % Nt;
    const int e  = idx / (Mt * Nt);
    const int m0 = mt * 128, n0 = nt * 128;

    const __half* A = (PHASE == 1) ? g_Xh  : g_Y;
    const __half* B = (PHASE == 1) ? g_W1h : g_W2T;
    const __half* Ab = A + (size_t)(e * CAP_ + m0) * KSEG;
    const __half* Bb = B + (size_t)(e * Ntot + n0) * KSEG;

    auto issue = [&](int c) {
        const int k0 = c * 64;
        const int st = c % STAGES;
        const uint32_t sA = sb + st * STB, sB = sA + 16384;
#pragma unroll
        for (int t = 0; t < 4; t++) {
            int i = t * 256 + tid, row = i >> 3, c16 = i & 7;
            cpa16(sA + row * 128 + ((c16 ^ (row & 7)) << 4),
                  Ab + (size_t)row * KSEG + k0 + c16 * 8);
        }
#pragma unroll
        for (int t = 0; t < 4; t++) {
            int i = t * 256 + tid, row = i >> 3, c16 = i & 7;
            cpa16(sB + row * 128 + ((c16 ^ (row & 7)) << 4),
                  Bb + (size_t)row * KSEG + k0 + c16 * 8);
        }
        asm volatile("cp.async.commit_group;" ::: "memory");
    };

    // warp tile: 32 (M) x 64 (N); warp grid 4x2
    const int m_off = (wid >> 1) * 32;
    const int n_off = (wid & 1) * 64;
    float acc[2][8][4] = {};

    issue(0);
    issue(1);
    asm volatile("cp.async.wait_group 1;" ::: "memory");
    __syncthreads();

    for (int c = 0; c < NCH; ++c) {
        const int st = c % STAGES;
        const uint32_t sA = sb + st * STB, sB = sA + 16384;
#pragma unroll
        for (int kk = 0; kk < 4; ++kk) {               // 4 x k16 per 64-chunk
            uint32_t aF[2][4];
#pragma unroll
            for (int i = 0; i < 2; ++i) {
                int row = m_off + 16 * i + (lane & 15);
                int ch  = kk * 2 + (lane >> 4);
                ldsm4(aF[i], sA + row * 128 + ((ch ^ (row & 7)) << 4));
            }
            uint32_t bF[4][4];
#pragma unroll
            for (int j4 = 0; j4 < 4; ++j4) {
                int row = n_off + 16 * j4 + ((lane >> 4) << 3) + (lane & 7);
                int ch  = kk * 2 + ((lane >> 3) & 1);
                ldsm4(bF[j4], sB + row * 128 + ((ch ^ (row & 7)) << 4));
            }
#pragma unroll
            for (int i = 0; i < 2; ++i)
#pragma unroll
                for (int j = 0; j < 8; ++j)
                    mma16816(acc[i][j], aF[i], bF[j >> 1][(j & 1) * 2], bF[j >> 1][(j & 1) * 2 + 1]);
        }
        if (c + 2 < NCH) issue(c + 2);
        else asm volatile("cp.async.commit_group;" ::: "memory");
        asm volatile("cp.async.wait_group 1;" ::: "memory");
        __syncthreads();
    }

    // ---- epilogue ----
    const int r_lane = lane >> 2;
    const int c_lane = (lane & 3) * 2;
    const float* brow = bias + (size_t)e * Ntot;
#pragma unroll
    for (int i = 0; i < 2; ++i) {
#pragma unroll
        for (int half = 0; half < 2; ++half) {
            const int m = m0 + m_off + 16 * i + r_lane + half * 8;
            if (PHASE == 1) {
                __half* yrow = g_Y + (size_t)(e * CAP_ + m) * H_;
#pragma unroll
                for (int j = 0; j < 8; ++j) {
                    const int col = n0 + n_off + 8 * j + c_lane;
                    float v0 = acc[i][j][half * 2 + 0] + brow[col];
                    float v1 = acc[i][j][half * 2 + 1] + brow[col + 1];
                    v0 = fmaxf(v0, 0.f);
                    v1 = fmaxf(v1, 0.f);
                    *(uint32_t*)(yrow + col) = h2u(__floats2half2_rn(v0, v1));
                }
            } else {
                float* orow = outF + (size_t)(e * CAP_ + m) * D_;
#pragma unroll
                for (int j = 0; j < 8; ++j) {
                    const int col = n0 + n_off + 8 * j + c_lane;
                    float2 f;
                    f.x = acc[i][j][half * 2 + 0] + brow[col];
                    f.y = acc[i][j][half * 2 + 1] + brow[col + 1];
                    *(float2*)(orow + col) = f;
                }
            }
        }
    }
}

// ---------------- launch ----------------
extern "C" void kernel_launch(void* const* d_in, const int* in_sizes, int n_in,
                              void* d_out, int out_size) {
    const float* x  = (const float*)d_in[0];   // [E, CAP, D]
    const float* w1 = (const float*)d_in[1];   // [E, H, D]
    const float* b1 = (const float*)d_in[2];   // [E, H]
    const float* w2 = (const float*)d_in[3];   // [E, H, D]
    const float* b2 = (const float*)d_in[4];   // [E, D]
    float* out = (float*)d_out;                // [E, CAP, D]

    cudaFuncSetAttribute(gemm_mma<1>, cudaFuncAttributeMaxDynamicSharedMemorySize, SMEM_TOT);
    cudaFuncSetAttribute(gemm_mma<2>, cudaFuncAttributeMaxDynamicSharedMemorySize, SMEM_TOT);

    // 1) conversions (destinations resolved in device code — no host refs to __device__ symbols)
    conv_f16<0><<<(E_ * CAP_ * D_ / 4) / 256, 256>>>(x);           // X  -> g_Xh
    conv_f16<1><<<(E_ * H_   * D_ / 4) / 256, 256>>>(w1);          // W1 -> g_W1h
    conv_w2t<<<dim3(D_ / 32, H_ / 32, E_), dim3(32, 8)>>>(w2);     // W2 -> g_W2T (transposed)

    // 2) GEMM1: relu(X W1^T + b1) -> g_Y (fp16)
    gemm_mma<1><<<E_ * (CAP_ / 128) * (H_ / 128), 256, SMEM_TOT>>>(b1, nullptr);

    // 3) GEMM2: Y W2 + b2 -> out (fp32)
    gemm_mma<2><<<E_ * (CAP_ / 128) * (D_ / 128), 256, SMEM_TOT>>>(b2, out);
}